// round 1
// baseline (speedup 1.0000x reference)
#include <cuda_runtime.h>
#include <math.h>

#define VCAB 50257
#define EDIM 256
#define HDIM 512
#define BATCH 64
#define SLEN 128
#define TLEN 64
#define TD 63            // decoder steps (T-1)
#define GDIM 2048        // 4*H

// ---------------- scratch (static device allocations; no cudaMalloc) ----------------
__device__ __align__(16) float g_benc[GDIM];
__device__ __align__(16) float g_bdec[GDIM];
__device__ __align__(16) float g_encX[SLEN * BATCH * EDIM];                 // [s][b][e]
__device__ __align__(16) float g_xprojE[(size_t)SLEN * BATCH * GDIM];       // [s][b][4H]
__device__ __align__(16) float g_decX[TD * BATCH * EDIM];                   // [t][b][e]
__device__ __align__(16) float g_decxp[(size_t)TD * BATCH * GDIM];          // [t][b][4H]
__device__ __align__(16) float g_encout[(size_t)BATCH * SLEN * HDIM];       // [b][s][h]
__device__ __align__(16) float g_encWe[(size_t)BATCH * SLEN * HDIM];        // [b][s][h]
__device__ __align__(16) float g_h[BATCH * HDIM];
__device__ __align__(16) float g_c[BATCH * HDIM];
__device__ __align__(16) float g_xcat[BATCH * 2 * HDIM];                    // [b][ h | context ]
__device__ __align__(16) float g_Wpack[(size_t)GDIM * 1024];                // [j][ Whh | Wih_ctx ]
__device__ __align__(16) float g_hc[(size_t)TD * BATCH * 1024];             // [t][b][ h | context ]
__device__ __align__(16) float g_gpart[(size_t)8 * BATCH * GDIM];           // split-K partials (gates)
__device__ __align__(16) float g_hwhp[(size_t)4 * BATCH * HDIM];            // split-K partials (hWh)

__device__ __forceinline__ float sigf(float x) { return 1.0f / (1.0f + expf(-x)); }

// ---------------- setup kernels ----------------
__global__ void k_bias(const float* __restrict__ ebih, const float* __restrict__ ebhh,
                       const float* __restrict__ dbih, const float* __restrict__ dbhh) {
    int j = blockIdx.x * blockDim.x + threadIdx.x;
    if (j < GDIM) {
        g_benc[j] = ebih[j] + ebhh[j];
        g_bdec[j] = dbih[j] + dbhh[j];
    }
}

__global__ void k_wpack(const float* __restrict__ dWih, const float* __restrict__ dWhh) {
    size_t idx = (size_t)blockIdx.x * blockDim.x + threadIdx.x;   // GDIM*1024 total
    if (idx >= (size_t)GDIM * 1024) return;
    int j = (int)(idx >> 10);
    int k = (int)(idx & 1023);
    g_Wpack[idx] = (k < HDIM) ? dWhh[(size_t)j * HDIM + k]
                              : dWih[(size_t)j * (EDIM + HDIM) + EDIM + (k - HDIM)];
}

__global__ void k_gather_enc(const float* __restrict__ emb, const int* __restrict__ src) {
    int m = blockIdx.x;          // m = s*64 + b, total 8192
    int e = threadIdx.x;         // 256
    int s = m >> 6, b = m & 63;
    int tok = src[b * SLEN + s];
    g_encX[(size_t)m * EDIM + e] = emb[(size_t)tok * EDIM + e];
}

__global__ void k_gather_dec(const float* __restrict__ emb, const int* __restrict__ trg) {
    int m = blockIdx.x;          // m = t*64 + b, total 4032
    int e = threadIdx.x;
    int t = m >> 6, b = m & 63;
    int tok = trg[b * TLEN + t];  // trg[:, :-1] -> t in [0,63)
    g_decX[(size_t)m * EDIM + e] = emb[(size_t)tok * EDIM + e];
}

__global__ void k_zero_hc() {
    int i = blockIdx.x * blockDim.x + threadIdx.x;
    if (i < BATCH * HDIM) { g_h[i] = 0.0f; g_c[i] = 0.0f; }
}

__global__ void k_zero_out(float* __restrict__ out) {
    size_t idx = (size_t)blockIdx.x * blockDim.x + threadIdx.x;
    if (idx >= (size_t)BATCH * VCAB) return;
    size_t b = idx / VCAB, v = idx % VCAB;
    out[b * (size_t)TLEN * VCAB + v] = 0.0f;   // t = 0 slab
}

__global__ void k_copy_h2xcat() {
    int b = blockIdx.x, j = threadIdx.x;
    g_xcat[b * 1024 + j] = g_h[b * HDIM + j];
}

// ---------------- generic tiled SGEMM: C[M,N] = A[M,K] @ B[N,K]^T + bias ----------------
// asel: 0=g_encX 1=g_decX 2=g_encout 3=g_hc
// csel: 0=g_xprojE 1=g_decxp 2=g_encWe 3=fc output (special scatter into d_out)
// bsel: 0=g_benc 1=g_bdec 2=param bias
__global__ void sgemm64(int M, int N, int K,
                        int asel, int lda,
                        const float* __restrict__ Bp, int ldb,
                        int csel, int ldc,
                        int bsel, const float* __restrict__ biasp,
                        float* __restrict__ Coutp) {
    const float* A = (asel == 0) ? g_encX : (asel == 1) ? g_decX : (asel == 2) ? g_encout : g_hc;
    float* C = (csel == 0) ? g_xprojE : (csel == 1) ? g_decxp : (csel == 2) ? g_encWe : Coutp;
    const float* bias = (bsel == 0) ? g_benc : (bsel == 1) ? g_bdec : biasp;

    __shared__ __align__(16) float As[16][64];
    __shared__ __align__(16) float Bs[16][64];

    const int tid = threadIdx.x;               // 256
    const int tx = tid & 15, ty = tid >> 4;
    const int m0 = blockIdx.y * 64, n0 = blockIdx.x * 64;
    const int lr = tid >> 2;                   // 0..63
    const int lk = (tid & 3) << 2;             // 0,4,8,12

    float acc[4][4];
#pragma unroll
    for (int i = 0; i < 4; i++)
#pragma unroll
        for (int j = 0; j < 4; j++) acc[i][j] = 0.0f;

    const bool brow_ok = (n0 + lr) < N;
    const float* Arow = A + (size_t)(m0 + lr) * lda;
    const float* Brow = Bp + (size_t)(n0 + lr) * ldb;

    for (int k0 = 0; k0 < K; k0 += 16) {
        float4 av = *reinterpret_cast<const float4*>(Arow + k0 + lk);
        float4 bv = make_float4(0.f, 0.f, 0.f, 0.f);
        if (brow_ok) bv = *reinterpret_cast<const float4*>(Brow + k0 + lk);
        As[lk + 0][lr] = av.x; As[lk + 1][lr] = av.y; As[lk + 2][lr] = av.z; As[lk + 3][lr] = av.w;
        Bs[lk + 0][lr] = bv.x; Bs[lk + 1][lr] = bv.y; Bs[lk + 2][lr] = bv.z; Bs[lk + 3][lr] = bv.w;
        __syncthreads();
#pragma unroll
        for (int kk = 0; kk < 16; kk++) {
            float4 a = *reinterpret_cast<const float4*>(&As[kk][ty << 2]);
            float4 b = *reinterpret_cast<const float4*>(&Bs[kk][tx << 2]);
            float ar[4] = {a.x, a.y, a.z, a.w};
            float br[4] = {b.x, b.y, b.z, b.w};
#pragma unroll
            for (int i = 0; i < 4; i++)
#pragma unroll
                for (int j = 0; j < 4; j++) acc[i][j] += ar[i] * br[j];
        }
        __syncthreads();
    }

#pragma unroll
    for (int i = 0; i < 4; i++) {
        int m = m0 + (ty << 2) + i;
#pragma unroll
        for (int j = 0; j < 4; j++) {
            int n = n0 + (tx << 2) + j;
            if (n < N) {
                float v = acc[i][j] + bias[n];
                if (csel != 3) {
                    C[(size_t)m * ldc + n] = v;
                } else {
                    // m = t*64 + b  ->  out[b][t+1][n]
                    int bb = m & 63, tt = m >> 6;
                    C[((size_t)bb * TLEN + (tt + 1)) * VCAB + n] = v;
                }
            }
        }
    }
}

// ---------------- split-K skinny GEMM (M=64): P[kz][64][N] = A[64, kslice] @ B[N, kslice]^T ----------------
// op: 0 = encoder gates (A=g_h, B=enc_Whh ldb=512, P=g_gpart)
//     1 = hWh          (A=g_h, B=attn_W  ldb=1024, P=g_hwhp)
//     2 = decoder gates(A=g_xcat lda=1024, B=g_Wpack ldb=1024, P=g_gpart)
__global__ void sgemm_sk(int N, int Kc, int op, const float* __restrict__ Bext) {
    const float* A; int lda; const float* Bm; int ldb; float* P;
    if (op == 0)      { A = g_h;    lda = HDIM; Bm = Bext;    ldb = HDIM;     P = g_gpart; }
    else if (op == 1) { A = g_h;    lda = HDIM; Bm = Bext;    ldb = 2 * HDIM; P = g_hwhp;  }
    else              { A = g_xcat; lda = 1024; Bm = g_Wpack; ldb = 1024;     P = g_gpart; }

    __shared__ __align__(16) float As[16][64];
    __shared__ __align__(16) float Bs[16][64];

    const int tid = threadIdx.x;
    const int tx = tid & 15, ty = tid >> 4;
    const int n0 = blockIdx.x * 64;
    const int kz = blockIdx.y;
    const int kbeg = kz * Kc, kend = kbeg + Kc;
    const int lr = tid >> 2;
    const int lk = (tid & 3) << 2;

    float acc[4][4];
#pragma unroll
    for (int i = 0; i < 4; i++)
#pragma unroll
        for (int j = 0; j < 4; j++) acc[i][j] = 0.0f;

    const float* Arow = A + (size_t)lr * lda;
    const float* Brow = Bm + (size_t)(n0 + lr) * ldb;

    for (int k0 = kbeg; k0 < kend; k0 += 16) {
        float4 av = *reinterpret_cast<const float4*>(Arow + k0 + lk);
        float4 bv = *reinterpret_cast<const float4*>(Brow + k0 + lk);
        As[lk + 0][lr] = av.x; As[lk + 1][lr] = av.y; As[lk + 2][lr] = av.z; As[lk + 3][lr] = av.w;
        Bs[lk + 0][lr] = bv.x; Bs[lk + 1][lr] = bv.y; Bs[lk + 2][lr] = bv.z; Bs[lk + 3][lr] = bv.w;
        __syncthreads();
#pragma unroll
        for (int kk = 0; kk < 16; kk++) {
            float4 a = *reinterpret_cast<const float4*>(&As[kk][ty << 2]);
            float4 b = *reinterpret_cast<const float4*>(&Bs[kk][tx << 2]);
            float ar[4] = {a.x, a.y, a.z, a.w};
            float br[4] = {b.x, b.y, b.z, b.w};
#pragma unroll
            for (int i = 0; i < 4; i++)
#pragma unroll
                for (int j = 0; j < 4; j++) acc[i][j] += ar[i] * br[j];
        }
        __syncthreads();
    }

#pragma unroll
    for (int i = 0; i < 4; i++) {
        int m = (ty << 2) + i;
#pragma unroll
        for (int j = 0; j < 4; j++) {
            int n = n0 + (tx << 2) + j;
            P[((size_t)kz * 64 + m) * N + n] = acc[i][j];
        }
    }
}

// ---------------- encoder LSTM elementwise step ----------------
__global__ void k_enc_lstm(int t) {
    int b = blockIdx.x, j = threadIdx.x;   // 64 x 512
    size_t base = ((size_t)t * BATCH + b) * GDIM;
    float gi = g_xprojE[base + j];
    float gf = g_xprojE[base + 512 + j];
    float gg = g_xprojE[base + 1024 + j];
    float go = g_xprojE[base + 1536 + j];
#pragma unroll
    for (int s2 = 0; s2 < 4; s2++) {
        const float* p = g_gpart + ((size_t)s2 * BATCH + b) * GDIM;
        gi += p[j]; gf += p[512 + j]; gg += p[1024 + j]; go += p[1536 + j];
    }
    int hi = b * HDIM + j;
    float c = sigf(gf) * g_c[hi] + sigf(gi) * tanhf(gg);
    float h = sigf(go) * tanhf(c);
    g_c[hi] = c;
    g_h[hi] = h;
    g_encout[((size_t)b * SLEN + t) * HDIM + j] = h;
}

// ---------------- fused attention: sum hWh partials, scores, softmax, context ----------------
__global__ void k_attn(const float* __restrict__ vw, int t) {
    int b = blockIdx.x;
    int tid = threadIdx.x;                 // 512
    __shared__ float hwh[HDIM];
    __shared__ float vws[HDIM];
    __shared__ float sc[SLEN];
    __shared__ float red[SLEN];

    float acc0 = 0.0f;
#pragma unroll
    for (int s2 = 0; s2 < 4; s2++) acc0 += g_hwhp[((size_t)s2 * BATCH + b) * HDIM + tid];
    hwh[tid] = acc0;
    vws[tid] = vw[tid];
    __syncthreads();

    int warp = tid >> 5, lane = tid & 31;
    for (int s = warp; s < SLEN; s += 16) {
        const float* we = &g_encWe[((size_t)b * SLEN + s) * HDIM];
        float acc = 0.0f;
        for (int j = lane; j < HDIM; j += 32)
            acc += tanhf(hwh[j] + we[j]) * vws[j];
#pragma unroll
        for (int o = 16; o > 0; o >>= 1) acc += __shfl_xor_sync(0xffffffffu, acc, o);
        if (lane == 0) sc[s] = acc;
    }
    __syncthreads();

    // softmax over 128
    if (tid < SLEN) red[tid] = sc[tid];
    __syncthreads();
    for (int o = 64; o > 0; o >>= 1) {
        if (tid < o) red[tid] = fmaxf(red[tid], red[tid + o]);
        __syncthreads();
    }
    float mx = red[0];
    __syncthreads();
    float e = 0.0f;
    if (tid < SLEN) { e = expf(sc[tid] - mx); red[tid] = e; }
    __syncthreads();
    for (int o = 64; o > 0; o >>= 1) {
        if (tid < o) red[tid] += red[tid + o];
        __syncthreads();
    }
    float inv = 1.0f / red[0];
    __syncthreads();
    if (tid < SLEN) sc[tid] = e * inv;
    __syncthreads();

    // context[j] = sum_s w[s] * enc_out[b][s][j]
    float ctx = 0.0f;
    const float* eo = &g_encout[(size_t)b * SLEN * HDIM];
    for (int s = 0; s < SLEN; s++) ctx += sc[s] * eo[(size_t)s * HDIM + tid];
    g_xcat[b * 1024 + HDIM + tid] = ctx;
    g_hc[((size_t)t * BATCH + b) * 1024 + HDIM + tid] = ctx;
}

// ---------------- decoder LSTM elementwise step ----------------
__global__ void k_dec_lstm(int t) {
    int b = blockIdx.x, j = threadIdx.x;
    size_t base = ((size_t)t * BATCH + b) * GDIM;
    float gi = g_decxp[base + j];
    float gf = g_decxp[base + 512 + j];
    float gg = g_decxp[base + 1024 + j];
    float go = g_decxp[base + 1536 + j];
#pragma unroll
    for (int s2 = 0; s2 < 8; s2++) {
        const float* p = g_gpart + ((size_t)s2 * BATCH + b) * GDIM;
        gi += p[j]; gf += p[512 + j]; gg += p[1024 + j]; go += p[1536 + j];
    }
    int hi = b * HDIM + j;
    float c = sigf(gf) * g_c[hi] + sigf(gi) * tanhf(gg);
    float h = sigf(go) * tanhf(c);
    g_c[hi] = c;
    g_h[hi] = h;
    g_xcat[b * 1024 + j] = h;
    g_hc[((size_t)t * BATCH + b) * 1024 + j] = h;
}

// ---------------- host driver ----------------
extern "C" void kernel_launch(void* const* d_in, const int* in_sizes, int n_in,
                              void* d_out, int out_size) {
    const int*   src     = (const int*)  d_in[0];
    const int*   trg     = (const int*)  d_in[1];
    const float* enc_emb = (const float*)d_in[2];
    const float* enc_Wih = (const float*)d_in[3];
    const float* enc_Whh = (const float*)d_in[4];
    const float* enc_bih = (const float*)d_in[5];
    const float* enc_bhh = (const float*)d_in[6];
    const float* dec_emb = (const float*)d_in[7];
    const float* dec_Wih = (const float*)d_in[8];
    const float* dec_Whh = (const float*)d_in[9];
    const float* dec_bih = (const float*)d_in[10];
    const float* dec_bhh = (const float*)d_in[11];
    const float* attn_W  = (const float*)d_in[12];
    const float* attn_b  = (const float*)d_in[13];
    const float* v_w     = (const float*)d_in[14];
    const float* fc_W    = (const float*)d_in[15];
    const float* fc_b    = (const float*)d_in[16];
    float* out = (float*)d_out;
    (void)in_sizes; (void)n_in; (void)out_size;

    // setup
    k_bias<<<8, 256>>>(enc_bih, enc_bhh, dec_bih, dec_bhh);
    k_wpack<<<(GDIM * 1024 + 255) / 256, 256>>>(dec_Wih, dec_Whh);
    k_gather_enc<<<SLEN * BATCH, EDIM>>>(enc_emb, src);
    k_gather_dec<<<TD * BATCH, EDIM>>>(dec_emb, trg);
    k_zero_hc<<<(BATCH * HDIM + 255) / 256, 256>>>();
    k_zero_out<<<((size_t)BATCH * VCAB + 255) / 256, 256>>>(out);

    // batched input projections
    // xprojE = encX @ enc_Wih^T + b_enc  [8192, 2048], K=256
    sgemm64<<<dim3(GDIM / 64, (SLEN * BATCH) / 64), 256>>>(
        SLEN * BATCH, GDIM, EDIM, /*asel*/0, EDIM, enc_Wih, EDIM,
        /*csel*/0, GDIM, /*bsel*/0, nullptr, nullptr);
    // decxp = decX @ dec_Wih[:, :256]^T + b_dec  [4032, 2048], K=256, ldb=768
    sgemm64<<<dim3(GDIM / 64, (TD * BATCH) / 64), 256>>>(
        TD * BATCH, GDIM, EDIM, /*asel*/1, EDIM, dec_Wih, EDIM + HDIM,
        /*csel*/1, GDIM, /*bsel*/1, nullptr, nullptr);

    // encoder recurrence
    for (int t = 0; t < SLEN; t++) {
        sgemm_sk<<<dim3(GDIM / 64, 4), 256>>>(GDIM, HDIM / 4, /*op*/0, enc_Whh);
        k_enc_lstm<<<BATCH, HDIM>>>(t);
    }

    // encWe = enc_out @ attn_W[:, H:]^T + attn_b  [8192, 512], K=512, ldb=1024
    sgemm64<<<dim3(HDIM / 64, (BATCH * SLEN) / 64), 256>>>(
        BATCH * SLEN, HDIM, HDIM, /*asel*/2, HDIM, attn_W + HDIM, 2 * HDIM,
        /*csel*/2, HDIM, /*bsel*/2, attn_b, nullptr);

    k_copy_h2xcat<<<BATCH, HDIM>>>();

    // decoder recurrence
    for (int t = 0; t < TD; t++) {
        // hWh = h @ attn_W[:, :H]^T  [64,512], K=512, split-K 4
        sgemm_sk<<<dim3(HDIM / 64, 4), 256>>>(HDIM, HDIM / 4, /*op*/1, attn_W);
        k_attn<<<BATCH, HDIM>>>(v_w, t);
        // gates = xcat @ Wpack^T  [64,2048], K=1024, split-K 8
        sgemm_sk<<<dim3(GDIM / 64, 8), 256>>>(GDIM, 1024 / 8, /*op*/2, nullptr);
        k_dec_lstm<<<BATCH, HDIM>>>(t);
    }

    // final fused output projection: preds = hc @ fc_W^T + fc_b  [4032, 50257], K=1024
    sgemm64<<<dim3((VCAB + 63) / 64, (TD * BATCH) / 64), 256>>>(
        TD * BATCH, VCAB, 1024, /*asel*/3, 1024, fc_W, 1024,
        /*csel*/3, 0, /*bsel*/2, fc_b, out);
}

// round 3
// speedup vs baseline: 2.7789x; 2.7789x over previous
#include <cuda_runtime.h>
#include <cuda_bf16.h>
#include <cuda_fp16.h>
#include <math.h>
#include <stdint.h>

#define VCAB 50257
#define EDIM 256
#define HDIM 512
#define BATCH 64
#define SLEN 128
#define TLEN 64
#define TD 63            // decoder steps (T-1)
#define GDIM 2048        // 4*H

// fc GEMM dims (fp16 mma.sync path)
#define KD 1024
#define MPAD 4096        // 4032 padded to 32x128
#define NPAD 50432       // 50257 padded to 394x128
#define KC 64            // k per chunk (128 bytes fp16)
#define NCHK 16          // KD / KC
#define STGB 32768       // stage bytes: A 16KB + B 16KB

// ---------------- scratch (static device allocations; no cudaMalloc) ----------------
__device__ __align__(16) float g_benc[GDIM];
__device__ __align__(16) float g_bdec[GDIM];
__device__ __align__(16) float g_encX[SLEN * BATCH * EDIM];
__device__ __align__(16) float g_xprojE[(size_t)SLEN * BATCH * GDIM];
__device__ __align__(16) float g_decX[TD * BATCH * EDIM];
__device__ __align__(16) float g_decxp[(size_t)TD * BATCH * GDIM];
__device__ __align__(16) float g_encout[(size_t)BATCH * SLEN * HDIM];
__device__ __align__(16) float g_encWe[(size_t)BATCH * SLEN * HDIM];
__device__ __align__(16) float g_h[BATCH * HDIM];
__device__ __align__(16) float g_c[BATCH * HDIM];
__device__ __align__(16) float g_xcat[BATCH * 2 * HDIM];
__device__ __align__(16) float g_Wpack[(size_t)GDIM * 1024];
__device__ __align__(16) float g_hc[(size_t)TD * BATCH * 1024];
__device__ __align__(16) float g_gpart[(size_t)8 * BATCH * GDIM];
__device__ __align__(16) float g_hwhp[(size_t)4 * BATCH * HDIM];
// fp16 operands for the tensor-core fc GEMM (pad rows stay zero: never written)
__device__ __align__(16) __half g_Ahf[(size_t)MPAD * KD];
__device__ __align__(16) __half g_Bhf[(size_t)NPAD * KD];

__device__ __forceinline__ float sigf(float x) { return 1.0f / (1.0f + expf(-x)); }

// ---------------- portable PTX helpers (compute_103-safe: sm_80-era ops only) ----------------
__device__ __forceinline__ uint32_t smem_u32(const void* p) {
    uint32_t a;
    asm("{ .reg .u64 t; cvta.to.shared.u64 t, %1; cvt.u32.u64 %0, t; }" : "=r"(a) : "l"(p));
    return a;
}
__device__ __forceinline__ void cpa16(uint32_t dst, const void* src) {
    asm volatile("cp.async.cg.shared.global [%0], [%1], 16;" :: "r"(dst), "l"(src) : "memory");
}
__device__ __forceinline__ void cpa_commit() { asm volatile("cp.async.commit_group;" ::: "memory"); }
template <int N> __device__ __forceinline__ void cpa_wait() {
    asm volatile("cp.async.wait_group %0;" :: "n"(N) : "memory");
}
#define LDMX4(r, addr) \
    asm volatile("ldmatrix.sync.aligned.m8n8.x4.shared.b16 {%0,%1,%2,%3}, [%4];" \
        : "=r"((r)[0]), "=r"((r)[1]), "=r"((r)[2]), "=r"((r)[3]) : "r"(addr))
__device__ __forceinline__ void mma16816(float* c, const uint32_t* a, uint32_t b0, uint32_t b1) {
    asm volatile("mma.sync.aligned.m16n8k16.row.col.f32.f16.f16.f32 "
        "{%0,%1,%2,%3}, {%4,%5,%6,%7}, {%8,%9}, {%0,%1,%2,%3};"
        : "+f"(c[0]), "+f"(c[1]), "+f"(c[2]), "+f"(c[3])
        : "r"(a[0]), "r"(a[1]), "r"(a[2]), "r"(a[3]), "r"(b0), "r"(b1));
}

// ---------------- setup kernels ----------------
__global__ void k_bias(const float* __restrict__ ebih, const float* __restrict__ ebhh,
                       const float* __restrict__ dbih, const float* __restrict__ dbhh) {
    int j = blockIdx.x * blockDim.x + threadIdx.x;
    if (j < GDIM) {
        g_benc[j] = ebih[j] + ebhh[j];
        g_bdec[j] = dbih[j] + dbhh[j];
    }
}

__global__ void k_wpack(const float* __restrict__ dWih, const float* __restrict__ dWhh) {
    size_t idx = (size_t)blockIdx.x * blockDim.x + threadIdx.x;
    if (idx >= (size_t)GDIM * 1024) return;
    int j = (int)(idx >> 10);
    int k = (int)(idx & 1023);
    g_Wpack[idx] = (k < HDIM) ? dWhh[(size_t)j * HDIM + k]
                              : dWih[(size_t)j * (EDIM + HDIM) + EDIM + (k - HDIM)];
}

__global__ void k_gather_enc(const float* __restrict__ emb, const int* __restrict__ src) {
    int m = blockIdx.x;
    int e = threadIdx.x;
    int s = m >> 6, b = m & 63;
    int tok = src[b * SLEN + s];
    g_encX[(size_t)m * EDIM + e] = emb[(size_t)tok * EDIM + e];
}

__global__ void k_gather_dec(const float* __restrict__ emb, const int* __restrict__ trg) {
    int m = blockIdx.x;
    int e = threadIdx.x;
    int t = m >> 6, b = m & 63;
    int tok = trg[b * TLEN + t];
    g_decX[(size_t)m * EDIM + e] = emb[(size_t)tok * EDIM + e];
}

__global__ void k_zero_hc() {
    int i = blockIdx.x * blockDim.x + threadIdx.x;
    if (i < BATCH * HDIM) { g_h[i] = 0.0f; g_c[i] = 0.0f; }
}

__global__ void k_zero_out(float* __restrict__ out) {
    size_t idx = (size_t)blockIdx.x * blockDim.x + threadIdx.x;
    if (idx >= (size_t)BATCH * VCAB) return;
    size_t b = idx / VCAB, v = idx % VCAB;
    out[b * (size_t)TLEN * VCAB + v] = 0.0f;
}

__global__ void k_copy_h2xcat() {
    int b = blockIdx.x, j = threadIdx.x;
    g_xcat[b * 1024 + j] = g_h[b * HDIM + j];
}

// ---------------- fp16 conversions ----------------
__global__ void k_convB_h(const float* __restrict__ W) {
    size_t i4 = (size_t)blockIdx.x * blockDim.x + threadIdx.x;   // processes 4 elems
    if (i4 * 4 >= (size_t)VCAB * KD) return;
    float4 v = *reinterpret_cast<const float4*>(W + i4 * 4);
    __half2* dst = reinterpret_cast<__half2*>(g_Bhf + i4 * 4);
    dst[0] = __floats2half2_rn(v.x, v.y);
    dst[1] = __floats2half2_rn(v.z, v.w);
}

__global__ void k_convA_h() {
    size_t i4 = (size_t)blockIdx.x * blockDim.x + threadIdx.x;
    if (i4 * 4 >= (size_t)TD * BATCH * KD) return;
    float4 v = *reinterpret_cast<const float4*>(g_hc + i4 * 4);
    __half2* dst = reinterpret_cast<__half2*>(g_Ahf + i4 * 4);
    dst[0] = __floats2half2_rn(v.x, v.y);
    dst[1] = __floats2half2_rn(v.z, v.w);
}

// ---------------- fp16 tensor-core fc GEMM (mma.sync, compute_103-portable) ----------------
// C[m][n] = A[m,:] . B[n,:] + fc_b[n], scattered to out[b][t+1][n].
// CTA tile 128x128, 8 warps in 2(M)x4(N), warp tile 64x32, 3-stage cp.async pipeline.
__global__ void __launch_bounds__(256, 1) hgemm_fc(const float* __restrict__ fc_b,
                                                   float* __restrict__ out) {
    extern __shared__ char sm[];
    const uint32_t sbase = smem_u32(sm);
    const int tid = threadIdx.x;
    const int wid = tid >> 5, lane = tid & 31;
    const int m0 = blockIdx.x * 128;
    const int n0 = blockIdx.y * 128;
    const int wm = wid >> 2;       // 0..1
    const int wn = wid & 3;        // 0..3

    const char* Ag = (const char*)g_Ahf + (size_t)m0 * (KD * 2);
    const char* Bg = (const char*)g_Bhf + (size_t)n0 * (KD * 2);

    float acc[4][4][4];
#pragma unroll
    for (int i = 0; i < 4; i++)
#pragma unroll
        for (int j = 0; j < 4; j++)
#pragma unroll
            for (int r = 0; r < 4; r++) acc[i][j][r] = 0.0f;

    // chunk loader: 2048 x 16B cp.async (A:1024, B:1024), 8 per thread, XOR-8 swizzle
    auto load_chunk = [&](int kc, int slot) {
        uint32_t st = sbase + (uint32_t)slot * STGB;
#pragma unroll
        for (int i = 0; i < 8; i++) {
            int idx = tid + (i << 8);               // 0..2047
            int isB = idx >> 10;
            int r = (idx & 1023) >> 3;              // row 0..127
            int seg = idx & 7;                      // 16B segment in 128B row
            uint32_t dst = st + (isB ? 16384u : 0u) + (uint32_t)(r << 7)
                         + (uint32_t)(((seg ^ (r & 7)) << 4));
            const char* src = (isB ? Bg : Ag) + (size_t)r * (KD * 2) + (size_t)kc * 128 + (seg << 4);
            cpa16(dst, src);
        }
        cpa_commit();
    };

    const int g = lane >> 3, lr = lane & 7;

    auto compute = [&](int slot) {
        uint32_t Abase = sbase + (uint32_t)slot * STGB;
        uint32_t Bbase = Abase + 16384u;
#pragma unroll
        for (int ks = 0; ks < 4; ks++) {
            uint32_t afr[4][4];
#pragma unroll
            for (int mt = 0; mt < 4; mt++) {
                int row = wm * 64 + mt * 16 + (g & 1) * 8 + lr;
                int kseg = ks * 2 + (g >> 1);
                uint32_t addr = Abase + (uint32_t)(row << 7) + (uint32_t)(((kseg ^ (row & 7)) << 4));
                LDMX4(afr[mt], addr);
            }
            uint32_t bfr[2][4];
#pragma unroll
            for (int np = 0; np < 2; np++) {
                int row = wn * 32 + np * 16 + (g >> 1) * 8 + lr;
                int kseg = ks * 2 + (g & 1);
                uint32_t addr = Bbase + (uint32_t)(row << 7) + (uint32_t)(((kseg ^ (row & 7)) << 4));
                LDMX4(bfr[np], addr);
            }
#pragma unroll
            for (int mt = 0; mt < 4; mt++)
#pragma unroll
                for (int nt = 0; nt < 4; nt++) {
                    const uint32_t* b = &bfr[nt >> 1][(nt & 1) * 2];
                    mma16816(acc[mt][nt], afr[mt], b[0], b[1]);
                }
        }
    };

    // 3-stage pipeline
    load_chunk(0, 0);
    load_chunk(1, 1);
    for (int i = 0; i < NCHK; i++) {
        if (i + 1 < NCHK) cpa_wait<1>(); else cpa_wait<0>();
        __syncthreads();
        if (i + 2 < NCHK) load_chunk(i + 2, (i + 2) % 3);
        compute(i % 3);
    }

    // epilogue: bias + scatter out[b][t+1][n]
    const int quad = lane >> 2, tq = lane & 3;
#pragma unroll
    for (int mt = 0; mt < 4; mt++) {
        int mr0 = m0 + wm * 64 + mt * 16 + quad;
#pragma unroll
        for (int half = 0; half < 2; half++) {
            int m = mr0 + half * 8;
            if (m >= TD * BATCH) continue;
            int bb = m & 63, tt = m >> 6;
            float* orow = out + ((size_t)bb * TLEN + (tt + 1)) * VCAB;
#pragma unroll
            for (int nt = 0; nt < 4; nt++) {
                int n = n0 + wn * 32 + nt * 8 + tq * 2;
                float v0 = acc[mt][nt][half * 2 + 0];
                float v1 = acc[mt][nt][half * 2 + 1];
                if (n < VCAB)     orow[n]     = v0 + fc_b[n];
                if (n + 1 < VCAB) orow[n + 1] = v1 + fc_b[n + 1];
            }
        }
    }
}

// ---------------- generic tiled SGEMM: C[M,N] = A[M,K] @ B[N,K]^T + bias ----------------
__global__ void sgemm64(int M, int N, int K,
                        int asel, int lda,
                        const float* __restrict__ Bp, int ldb,
                        int csel, int ldc,
                        int bsel, const float* __restrict__ biasp,
                        float* __restrict__ Coutp) {
    const float* A = (asel == 0) ? g_encX : (asel == 1) ? g_decX : (asel == 2) ? g_encout : g_hc;
    float* C = (csel == 0) ? g_xprojE : (csel == 1) ? g_decxp : (csel == 2) ? g_encWe : Coutp;
    const float* bias = (bsel == 0) ? g_benc : (bsel == 1) ? g_bdec : biasp;

    __shared__ __align__(16) float As[16][64];
    __shared__ __align__(16) float Bs[16][64];

    const int tid = threadIdx.x;
    const int tx = tid & 15, ty = tid >> 4;
    const int m0 = blockIdx.y * 64, n0 = blockIdx.x * 64;
    const int lr = tid >> 2;
    const int lk = (tid & 3) << 2;

    float acc[4][4];
#pragma unroll
    for (int i = 0; i < 4; i++)
#pragma unroll
        for (int j = 0; j < 4; j++) acc[i][j] = 0.0f;

    const bool brow_ok = (n0 + lr) < N;
    const float* Arow = A + (size_t)(m0 + lr) * lda;
    const float* Brow = Bp + (size_t)(n0 + lr) * ldb;

    for (int k0 = 0; k0 < K; k0 += 16) {
        float4 av = *reinterpret_cast<const float4*>(Arow + k0 + lk);
        float4 bv = make_float4(0.f, 0.f, 0.f, 0.f);
        if (brow_ok) bv = *reinterpret_cast<const float4*>(Brow + k0 + lk);
        As[lk + 0][lr] = av.x; As[lk + 1][lr] = av.y; As[lk + 2][lr] = av.z; As[lk + 3][lr] = av.w;
        Bs[lk + 0][lr] = bv.x; Bs[lk + 1][lr] = bv.y; Bs[lk + 2][lr] = bv.z; Bs[lk + 3][lr] = bv.w;
        __syncthreads();
#pragma unroll
        for (int kk = 0; kk < 16; kk++) {
            float4 a = *reinterpret_cast<const float4*>(&As[kk][ty << 2]);
            float4 b = *reinterpret_cast<const float4*>(&Bs[kk][tx << 2]);
            float ar[4] = {a.x, a.y, a.z, a.w};
            float br[4] = {b.x, b.y, b.z, b.w};
#pragma unroll
            for (int i = 0; i < 4; i++)
#pragma unroll
                for (int j = 0; j < 4; j++) acc[i][j] += ar[i] * br[j];
        }
        __syncthreads();
    }

#pragma unroll
    for (int i = 0; i < 4; i++) {
        int m = m0 + (ty << 2) + i;
#pragma unroll
        for (int j = 0; j < 4; j++) {
            int n = n0 + (tx << 2) + j;
            if (n < N) C[(size_t)m * ldc + n] = acc[i][j] + bias[n];
        }
    }
}

// ---------------- split-K skinny GEMM (M=64) ----------------
__global__ void sgemm_sk(int N, int Kc, int op, const float* __restrict__ Bext) {
    const float* A; int lda; const float* Bm; int ldb; float* P;
    if (op == 0)      { A = g_h;    lda = HDIM; Bm = Bext;    ldb = HDIM;     P = g_gpart; }
    else if (op == 1) { A = g_h;    lda = HDIM; Bm = Bext;    ldb = 2 * HDIM; P = g_hwhp;  }
    else              { A = g_xcat; lda = 1024; Bm = g_Wpack; ldb = 1024;     P = g_gpart; }

    __shared__ __align__(16) float As[16][64];
    __shared__ __align__(16) float Bs[16][64];

    const int tid = threadIdx.x;
    const int tx = tid & 15, ty = tid >> 4;
    const int n0 = blockIdx.x * 64;
    const int kz = blockIdx.y;
    const int kbeg = kz * Kc, kend = kbeg + Kc;
    const int lr = tid >> 2;
    const int lk = (tid & 3) << 2;

    float acc[4][4];
#pragma unroll
    for (int i = 0; i < 4; i++)
#pragma unroll
        for (int j = 0; j < 4; j++) acc[i][j] = 0.0f;

    const float* Arow = A + (size_t)lr * lda;
    const float* Brow = Bm + (size_t)(n0 + lr) * ldb;

    for (int k0 = kbeg; k0 < kend; k0 += 16) {
        float4 av = *reinterpret_cast<const float4*>(Arow + k0 + lk);
        float4 bv = *reinterpret_cast<const float4*>(Brow + k0 + lk);
        As[lk + 0][lr] = av.x; As[lk + 1][lr] = av.y; As[lk + 2][lr] = av.z; As[lk + 3][lr] = av.w;
        Bs[lk + 0][lr] = bv.x; Bs[lk + 1][lr] = bv.y; Bs[lk + 2][lr] = bv.z; Bs[lk + 3][lr] = bv.w;
        __syncthreads();
#pragma unroll
        for (int kk = 0; kk < 16; kk++) {
            float4 a = *reinterpret_cast<const float4*>(&As[kk][ty << 2]);
            float4 b = *reinterpret_cast<const float4*>(&Bs[kk][tx << 2]);
            float ar[4] = {a.x, a.y, a.z, a.w};
            float br[4] = {b.x, b.y, b.z, b.w};
#pragma unroll
            for (int i = 0; i < 4; i++)
#pragma unroll
                for (int j = 0; j < 4; j++) acc[i][j] += ar[i] * br[j];
        }
        __syncthreads();
    }

#pragma unroll
    for (int i = 0; i < 4; i++) {
        int m = (ty << 2) + i;
#pragma unroll
        for (int j = 0; j < 4; j++) {
            int n = n0 + (tx << 2) + j;
            P[((size_t)kz * 64 + m) * N + n] = acc[i][j];
        }
    }
}

// ---------------- encoder LSTM elementwise step ----------------
__global__ void k_enc_lstm(int t) {
    int b = blockIdx.x, j = threadIdx.x;
    size_t base = ((size_t)t * BATCH + b) * GDIM;
    float gi = g_xprojE[base + j];
    float gf = g_xprojE[base + 512 + j];
    float gg = g_xprojE[base + 1024 + j];
    float go = g_xprojE[base + 1536 + j];
#pragma unroll
    for (int s2 = 0; s2 < 4; s2++) {
        const float* p = g_gpart + ((size_t)s2 * BATCH + b) * GDIM;
        gi += p[j]; gf += p[512 + j]; gg += p[1024 + j]; go += p[1536 + j];
    }
    int hi = b * HDIM + j;
    float c = sigf(gf) * g_c[hi] + sigf(gi) * tanhf(gg);
    float h = sigf(go) * tanhf(c);
    g_c[hi] = c;
    g_h[hi] = h;
    g_encout[((size_t)b * SLEN + t) * HDIM + j] = h;
}

// ---------------- fused attention ----------------
__global__ void k_attn(const float* __restrict__ vw, int t) {
    int b = blockIdx.x;
    int tid = threadIdx.x;
    __shared__ float hwh[HDIM];
    __shared__ float vws[HDIM];
    __shared__ float sc[SLEN];
    __shared__ float red[SLEN];

    float acc0 = 0.0f;
#pragma unroll
    for (int s2 = 0; s2 < 4; s2++) acc0 += g_hwhp[((size_t)s2 * BATCH + b) * HDIM + tid];
    hwh[tid] = acc0;
    vws[tid] = vw[tid];
    __syncthreads();

    int warp = tid >> 5, lane = tid & 31;
    for (int s = warp; s < SLEN; s += 16) {
        const float* we = &g_encWe[((size_t)b * SLEN + s) * HDIM];
        float acc = 0.0f;
        for (int j = lane; j < HDIM; j += 32)
            acc += tanhf(hwh[j] + we[j]) * vws[j];
#pragma unroll
        for (int o = 16; o > 0; o >>= 1) acc += __shfl_xor_sync(0xffffffffu, acc, o);
        if (lane == 0) sc[s] = acc;
    }
    __syncthreads();

    if (tid < SLEN) red[tid] = sc[tid];
    __syncthreads();
    for (int o = 64; o > 0; o >>= 1) {
        if (tid < o) red[tid] = fmaxf(red[tid], red[tid + o]);
        __syncthreads();
    }
    float mx = red[0];
    __syncthreads();
    float e = 0.0f;
    if (tid < SLEN) { e = expf(sc[tid] - mx); red[tid] = e; }
    __syncthreads();
    for (int o = 64; o > 0; o >>= 1) {
        if (tid < o) red[tid] += red[tid + o];
        __syncthreads();
    }
    float inv = 1.0f / red[0];
    __syncthreads();
    if (tid < SLEN) sc[tid] = e * inv;
    __syncthreads();

    float ctx = 0.0f;
    const float* eo = &g_encout[(size_t)b * SLEN * HDIM];
    for (int s = 0; s < SLEN; s++) ctx += sc[s] * eo[(size_t)s * HDIM + tid];
    g_xcat[b * 1024 + HDIM + tid] = ctx;
    g_hc[((size_t)t * BATCH + b) * 1024 + HDIM + tid] = ctx;
}

// ---------------- decoder LSTM elementwise step ----------------
__global__ void k_dec_lstm(int t) {
    int b = blockIdx.x, j = threadIdx.x;
    size_t base = ((size_t)t * BATCH + b) * GDIM;
    float gi = g_decxp[base + j];
    float gf = g_decxp[base + 512 + j];
    float gg = g_decxp[base + 1024 + j];
    float go = g_decxp[base + 1536 + j];
#pragma unroll
    for (int s2 = 0; s2 < 8; s2++) {
        const float* p = g_gpart + ((size_t)s2 * BATCH + b) * GDIM;
        gi += p[j]; gf += p[512 + j]; gg += p[1024 + j]; go += p[1536 + j];
    }
    int hi = b * HDIM + j;
    float c = sigf(gf) * g_c[hi] + sigf(gi) * tanhf(gg);
    float h = sigf(go) * tanhf(c);
    g_c[hi] = c;
    g_h[hi] = h;
    g_xcat[b * 1024 + j] = h;
    g_hc[((size_t)t * BATCH + b) * 1024 + j] = h;
}

// ---------------- host driver ----------------
extern "C" void kernel_launch(void* const* d_in, const int* in_sizes, int n_in,
                              void* d_out, int out_size) {
    const int*   src     = (const int*)  d_in[0];
    const int*   trg     = (const int*)  d_in[1];
    const float* enc_emb = (const float*)d_in[2];
    const float* enc_Wih = (const float*)d_in[3];
    const float* enc_Whh = (const float*)d_in[4];
    const float* enc_bih = (const float*)d_in[5];
    const float* enc_bhh = (const float*)d_in[6];
    const float* dec_emb = (const float*)d_in[7];
    const float* dec_Wih = (const float*)d_in[8];
    const float* dec_Whh = (const float*)d_in[9];
    const float* dec_bih = (const float*)d_in[10];
    const float* dec_bhh = (const float*)d_in[11];
    const float* attn_W  = (const float*)d_in[12];
    const float* attn_b  = (const float*)d_in[13];
    const float* v_w     = (const float*)d_in[14];
    const float* fc_W    = (const float*)d_in[15];
    const float* fc_b    = (const float*)d_in[16];
    float* out = (float*)d_out;
    (void)in_sizes; (void)n_in; (void)out_size;

    cudaFuncSetAttribute(hgemm_fc, cudaFuncAttributeMaxDynamicSharedMemorySize, 3 * STGB);

    // setup
    k_bias<<<8, 256>>>(enc_bih, enc_bhh, dec_bih, dec_bhh);
    k_wpack<<<(GDIM * 1024 + 255) / 256, 256>>>(dec_Wih, dec_Whh);
    k_gather_enc<<<SLEN * BATCH, EDIM>>>(enc_emb, src);
    k_gather_dec<<<TD * BATCH, EDIM>>>(dec_emb, trg);
    k_zero_hc<<<(BATCH * HDIM + 255) / 256, 256>>>();
    k_zero_out<<<((size_t)BATCH * VCAB + 255) / 256, 256>>>(out);
    // fc_W -> fp16 (independent of recurrence; do it early)
    k_convB_h<<<(int)(((size_t)VCAB * KD / 4 + 255) / 256), 256>>>(fc_W);

    // batched input projections
    sgemm64<<<dim3(GDIM / 64, (SLEN * BATCH) / 64), 256>>>(
        SLEN * BATCH, GDIM, EDIM, 0, EDIM, enc_Wih, EDIM, 0, GDIM, 0, nullptr, nullptr);
    sgemm64<<<dim3(GDIM / 64, (TD * BATCH) / 64), 256>>>(
        TD * BATCH, GDIM, EDIM, 1, EDIM, dec_Wih, EDIM + HDIM, 1, GDIM, 1, nullptr, nullptr);

    // encoder recurrence
    for (int t = 0; t < SLEN; t++) {
        sgemm_sk<<<dim3(GDIM / 64, 4), 256>>>(GDIM, HDIM / 4, 0, enc_Whh);
        k_enc_lstm<<<BATCH, HDIM>>>(t);
    }

    // encWe = enc_out @ attn_W[:, H:]^T + attn_b
    sgemm64<<<dim3(HDIM / 64, (BATCH * SLEN) / 64), 256>>>(
        BATCH * SLEN, HDIM, HDIM, 2, HDIM, attn_W + HDIM, 2 * HDIM, 2, HDIM, 2, attn_b, nullptr);

    k_copy_h2xcat<<<BATCH, HDIM>>>();

    // decoder recurrence
    for (int t = 0; t < TD; t++) {
        sgemm_sk<<<dim3(HDIM / 64, 4), 256>>>(HDIM, HDIM / 4, 1, attn_W);
        k_attn<<<BATCH, HDIM>>>(v_w, t);
        sgemm_sk<<<dim3(GDIM / 64, 8), 256>>>(GDIM, 1024 / 8, 2, nullptr);
        k_dec_lstm<<<BATCH, HDIM>>>(t);
    }

    // hc -> fp16, then tensor-core fc GEMM
    k_convA_h<<<(int)(((size_t)TD * BATCH * KD / 4 + 255) / 256), 256>>>();
    hgemm_fc<<<dim3(MPAD / 128, NPAD / 128), 256, 3 * STGB>>>(fc_b, out);
}